// round 7
// baseline (speedup 1.0000x reference)
#include <cuda_runtime.h>

// Problem constants (shapes fixed by the reference).
#define NNODES 100000
#define INDIM  512
#define HIDDIM 256
#define OUTDIM 64
#define NEDGES 3200000

// ---------------------------------------------------------------------------
// Scratch (device globals — no runtime allocation allowed)
// ---------------------------------------------------------------------------
__device__ __align__(16) float g_deg [NNODES];
__device__ __align__(16) float g_dinv[NNODES];
__device__ __align__(16) int2  g_esd [NEDGES];          // (src, dst) int32
__device__ __align__(16) float g_enorm[NEDGES];         // dinv[src]*dinv[dst]
__device__ __align__(16) float g_h  [NNODES * HIDDIM];  // x @ W1
__device__ __align__(16) float g_a1 [NNODES * HIDDIM];  // aggregated layer-1
__device__ __align__(16) float g_h2 [NNODES * OUTDIM];  // relu(a1) @ W2
__device__ int g_is64;                                   // edge dtype flag

// ---------------------------------------------------------------------------
// Edge dtype detection: int64 node ids are all < N; int32 data reinterpreted
// as int64 produces huge values (hi word = next node id) with certainty over
// 1024 samples. One thread, device-side, deterministic.
// ---------------------------------------------------------------------------
__global__ void k_detect(const void* __restrict__ ei, int E, int n) {
    if (blockIdx.x != 0 || threadIdx.x != 0) return;
    const long long* p = (const long long*)ei;
    int m = E < 1024 ? E : 1024;
    int ok = 1;
    for (int i = 0; i < m; i++) {
        long long v = p[i];
        if (v < 0 || v >= (long long)n) { ok = 0; break; }
    }
    g_is64 = ok;
}

__device__ __forceinline__ int edge_at(const void* ei, long long idx) {
    if (g_is64) return (int)((const long long*)ei)[idx];
    return ((const int*)ei)[idx];
}

// ---------------------------------------------------------------------------
// Degree / normalization prep
// ---------------------------------------------------------------------------
__global__ void k_deg_init(int n) {
    int i = blockIdx.x * blockDim.x + threadIdx.x;
    if (i < n) g_deg[i] = 1.0f;   // self loop
}

__global__ void k_deg_count(const void* __restrict__ ei, int E) {
    int e = blockIdx.x * blockDim.x + threadIdx.x;
    if (e < E) {
        int d = edge_at(ei, (long long)E + e);   // dst row
        atomicAdd(&g_deg[d], 1.0f);
    }
}

__global__ void k_dinv(int n) {
    int i = blockIdx.x * blockDim.x + threadIdx.x;
    if (i < n) g_dinv[i] = rsqrtf(g_deg[i]);   // deg >= 1 always
}

__global__ void k_prep(const void* __restrict__ ei, int E) {
    int e = blockIdx.x * blockDim.x + threadIdx.x;
    if (e < E) {
        int s = edge_at(ei, e);
        int d = edge_at(ei, (long long)E + e);
        g_esd[e]   = make_int2(s, d);
        g_enorm[e] = g_dinv[s] * g_dinv[d];
    }
}

// ---------------------------------------------------------------------------
// SGEMM, fp32 with packed f32x2 FMA (sm_103a FFMA2 path).
// A: [M,K] row-major, B: [K,N] row-major, C: [M,N] row-major.
// Requires: K % BK == 0, N % BN == 0, TM % 4 == 0, TN even.
// RELU_A applies relu to A elements on load (fuses layer-2's relu).
// ---------------------------------------------------------------------------
template <int BM, int BN, int BK, int TM, int TN, bool RELU_A>
__global__ __launch_bounds__((BM / TM) * (BN / TN))
void sgemm_k(const float* __restrict__ A, const float* __restrict__ B,
             float* __restrict__ C, int M, int N, int K)
{
    constexpr int NT  = (BM / TM) * (BN / TN);
    constexpr int TN2 = TN / 2;

    __shared__ __align__(16) float As[BK][BM];   // transposed: As[k][m]
    __shared__ __align__(16) float Bs[BK][BN];

    const int tid = threadIdx.x;
    const int tx  = tid % (BN / TN);
    const int ty  = tid / (BN / TN);
    const int m0  = blockIdx.y * BM;
    const int n0  = blockIdx.x * BN;

    unsigned long long acc[TM][TN2];
#pragma unroll
    for (int i = 0; i < TM; i++)
#pragma unroll
        for (int j = 0; j < TN2; j++) acc[i][j] = 0ull;

    for (int kk = 0; kk < K; kk += BK) {
        // A tile (float4 global loads, transposed scalar smem stores)
        for (int i = tid; i < BM * BK / 4; i += NT) {
            int r = i / (BK / 4);
            int c = (i % (BK / 4)) * 4;
            float4 v = make_float4(0.f, 0.f, 0.f, 0.f);
            int row = m0 + r;
            if (row < M)
                v = *reinterpret_cast<const float4*>(
                        &A[(long long)row * K + kk + c]);
            if (RELU_A) {
                v.x = fmaxf(v.x, 0.f); v.y = fmaxf(v.y, 0.f);
                v.z = fmaxf(v.z, 0.f); v.w = fmaxf(v.w, 0.f);
            }
            As[c + 0][r] = v.x; As[c + 1][r] = v.y;
            As[c + 2][r] = v.z; As[c + 3][r] = v.w;
        }
        // B tile (float4 both ways)
        for (int i = tid; i < BK * BN / 4; i += NT) {
            int r = i / (BN / 4);
            int c = (i % (BN / 4)) * 4;
            *reinterpret_cast<float4*>(&Bs[r][c]) =
                *reinterpret_cast<const float4*>(
                    &B[(long long)(kk + r) * N + n0 + c]);
        }
        __syncthreads();

#pragma unroll
        for (int k = 0; k < BK; k++) {
            float a[TM];
#pragma unroll
            for (int i = 0; i < TM; i += 4) {
                float4 av = *reinterpret_cast<const float4*>(&As[k][ty * TM + i]);
                a[i] = av.x; a[i + 1] = av.y; a[i + 2] = av.z; a[i + 3] = av.w;
            }
            unsigned long long b2[TN2];
            const unsigned long long* bp =
                reinterpret_cast<const unsigned long long*>(&Bs[k][tx * TN]);
#pragma unroll
            for (int j = 0; j < TN2; j++) b2[j] = bp[j];
#pragma unroll
            for (int i = 0; i < TM; i++) {
                unsigned long long a2;
                unsigned int au = __float_as_uint(a[i]);
                asm("mov.b64 %0, {%1, %1};" : "=l"(a2) : "r"(au));
#pragma unroll
                for (int j = 0; j < TN2; j++) {
                    asm("fma.rn.f32x2 %0, %1, %2, %3;"
                        : "=l"(acc[i][j])
                        : "l"(a2), "l"(b2[j]), "l"(acc[i][j]));
                }
            }
        }
        __syncthreads();
    }

#pragma unroll
    for (int i = 0; i < TM; i++) {
        int row = m0 + ty * TM + i;
        if (row >= M) continue;
        float* cp = &C[(long long)row * N + n0 + tx * TN];
#pragma unroll
        for (int j = 0; j < TN2; j++) {
            unsigned int lo, hi;
            asm("mov.b64 {%0, %1}, %2;" : "=r"(lo), "=r"(hi) : "l"(acc[i][j]));
            *reinterpret_cast<float2*>(cp + 2 * j) =
                make_float2(__uint_as_float(lo), __uint_as_float(hi));
        }
    }
}

// ---------------------------------------------------------------------------
// Self-loop init: out[i,:] = dinv[i]^2 * h[i,:]   (also initializes output,
// eliminating both a zero-fill pass and N self-loop edges)
// D4 = feature_dim / 4
// ---------------------------------------------------------------------------
template <int D4>
__global__ void k_selfinit(const float4* __restrict__ h4,
                           float4* __restrict__ o4, int total) {
    int gid = blockIdx.x * blockDim.x + threadIdx.x;
    if (gid >= total) return;
    int i = gid / D4;
    float w = g_dinv[i];
    w = w * w;
    float4 v = h4[gid];
    v.x *= w; v.y *= w; v.z *= w; v.w *= w;
    o4[gid] = v;
}

// ---------------------------------------------------------------------------
// Edge scatter: out[dst,:] += norm * h[src,:]
// One thread per (edge, float4-chunk). Warp lanes cover consecutive chunks of
// one edge -> coalesced 512B gather + coalesced RED bursts; the (src,dst,norm)
// loads are same-address within the warp -> L1 broadcast.
// ---------------------------------------------------------------------------
template <int D4>
__global__ void k_scatter(const float4* __restrict__ h4,
                          float* __restrict__ out, int total) {
    int gid = blockIdx.x * blockDim.x + threadIdx.x;
    if (gid >= total) return;
    int e = gid / D4;
    int c = gid - e * D4;
    int2  sd = g_esd[e];
    float w  = g_enorm[e];
    float4 v = h4[sd.x * D4 + c];
    float* o = out + ((long long)sd.y * D4 + c) * 4;
    atomicAdd(o + 0, w * v.x);   // return ignored -> REDG
    atomicAdd(o + 1, w * v.y);
    atomicAdd(o + 2, w * v.z);
    atomicAdd(o + 3, w * v.w);
}

// ---------------------------------------------------------------------------
// Launch
// ---------------------------------------------------------------------------
extern "C" void kernel_launch(void* const* d_in, const int* in_sizes, int n_in,
                              void* d_out, int out_size)
{
    const float* x   = (const float*)d_in[0];   // [N, 512]
    const float* W1  = (const float*)d_in[1];   // [512, 256]
    const float* W2  = (const float*)d_in[2];   // [256, 64]
    const void*  ei  = d_in[3];                 // [2, E] int32 or int64
    float*       out = (float*)d_out;           // [N, 64]

    const int N = in_sizes[0] / INDIM;
    const int E = in_sizes[3] / 2;

    void *ph, *pa1, *ph2;
    cudaGetSymbolAddress(&ph,  g_h);
    cudaGetSymbolAddress(&pa1, g_a1);
    cudaGetSymbolAddress(&ph2, g_h2);
    float* h  = (float*)ph;
    float* a1 = (float*)pa1;
    float* h2 = (float*)ph2;

    const int TB = 256;

    // --- edge dtype detection + normalization prep ---
    k_detect   <<<1, 32>>>(ei, E, N);
    k_deg_init <<<(N + TB - 1) / TB, TB>>>(N);
    k_deg_count<<<(E + TB - 1) / TB, TB>>>(ei, E);
    k_dinv     <<<(N + TB - 1) / TB, TB>>>(N);
    k_prep     <<<(E + TB - 1) / TB, TB>>>(ei, E);

    // --- layer 1: h = x @ W1 ---
    {
        dim3 grid(HIDDIM / 128, (N + 127) / 128);
        sgemm_k<128, 128, 8, 8, 8, false><<<grid, 256>>>(x, W1, h, N, HIDDIM, INDIM);
    }
    // a1 = dinv^2 * h (self loops), then += edges
    {
        int total = N * (HIDDIM / 4);
        k_selfinit<HIDDIM / 4><<<(total + TB - 1) / TB, TB>>>(
            (const float4*)h, (float4*)a1, total);
        int etot = E * (HIDDIM / 4);
        k_scatter<HIDDIM / 4><<<(etot + TB - 1) / TB, TB>>>(
            (const float4*)h, a1, etot);
    }

    // --- layer 2: h2 = relu(a1) @ W2 (relu fused into A load) ---
    {
        dim3 grid(OUTDIM / 64, (N + 127) / 128);
        sgemm_k<128, 64, 8, 8, 4, true><<<grid, 256>>>(a1, W2, h2, N, OUTDIM, HIDDIM);
    }
    // out = dinv^2 * h2, then += edges
    {
        int total = N * (OUTDIM / 4);
        k_selfinit<OUTDIM / 4><<<(total + TB - 1) / TB, TB>>>(
            (const float4*)h2, (float4*)out, total);
        int etot = E * (OUTDIM / 4);
        k_scatter<OUTDIM / 4><<<(etot + TB - 1) / TB, TB>>>(
            (const float4*)h2, out, etot);
    }
}

// round 8
// speedup vs baseline: 2.8301x; 2.8301x over previous
#include <cuda_runtime.h>

// Problem constants (shapes fixed by the reference).
#define NNODES 100000
#define INDIM  512
#define HIDDIM 256
#define OUTDIM 64
#define NEDGES 3200000

// ---------------------------------------------------------------------------
// Scratch (device globals — no runtime allocation allowed)
// ---------------------------------------------------------------------------
__device__ __align__(16) float g_dinv[NNODES];
__device__ __align__(16) int   g_cnt [NNODES];          // in-degree (no self loop)
__device__ __align__(16) int   g_off [NNODES];          // CSR exclusive offsets
__device__ __align__(16) int   g_pos [NNODES];          // placement cursors
__device__ __align__(16) int   g_part[1024];            // scan block partials
__device__ __align__(16) int   g_ssrc [NEDGES];         // dst-sorted: src id
__device__ __align__(16) float g_snorm[NEDGES];         // dst-sorted: edge norm
__device__ __align__(16) float g_h  [NNODES * HIDDIM];  // x @ W1
__device__ __align__(16) float g_a1 [NNODES * HIDDIM];  // aggregated layer-1
__device__ __align__(16) float g_h2 [NNODES * OUTDIM];  // relu(a1) @ W2
__device__ int g_is64;                                   // edge dtype flag

// ---------------------------------------------------------------------------
// Edge dtype detection (int64 vs int32 edge_index), parallel within 1 block.
// ---------------------------------------------------------------------------
__global__ void k_detect(const void* __restrict__ ei, int E, int n) {
    int m = E < 1024 ? E : 1024;
    int ok = 1;
    const long long* p = (const long long*)ei;
    for (int i = threadIdx.x; i < m; i += blockDim.x) {
        long long v = p[i];
        if (v < 0 || v >= (long long)n) ok = 0;
    }
    int all = __syncthreads_and(ok);
    if (threadIdx.x == 0) g_is64 = all;
}

__device__ __forceinline__ int edge_at(const void* ei, long long idx) {
    if (g_is64) return (int)((const long long*)ei)[idx];
    return ((const int*)ei)[idx];
}

// ---------------------------------------------------------------------------
// Degree count + CSR build (bucketed by dst)
// ---------------------------------------------------------------------------
__global__ void k_init(int n) {
    int i = blockIdx.x * blockDim.x + threadIdx.x;
    if (i < n) g_cnt[i] = 0;
}

__global__ void k_count(const void* __restrict__ ei, int E) {
    int e = blockIdx.x * blockDim.x + threadIdx.x;
    if (e < E) {
        int d = edge_at(ei, (long long)E + e);
        atomicAdd(&g_cnt[d], 1);
    }
}

__global__ void k_dinv(int n) {
    int i = blockIdx.x * blockDim.x + threadIdx.x;
    if (i < n) g_dinv[i] = rsqrtf(1.0f + (float)g_cnt[i]);  // +1 self loop
}

// Exclusive scan of g_cnt into g_off (3 phases, 1024-wide blocks).
__global__ void k_scan1(int n) {
    __shared__ int s[1024];
    int i = blockIdx.x * 1024 + threadIdx.x;
    int v = (i < n) ? g_cnt[i] : 0;
    s[threadIdx.x] = v;
    __syncthreads();
#pragma unroll
    for (int d = 1; d < 1024; d <<= 1) {
        int t = (threadIdx.x >= d) ? s[threadIdx.x - d] : 0;
        __syncthreads();
        s[threadIdx.x] += t;
        __syncthreads();
    }
    if (i < n) g_off[i] = s[threadIdx.x] - v;           // exclusive within block
    if (threadIdx.x == 1023) g_part[blockIdx.x] = s[1023];
}

__global__ void k_scan2(int nb) {
    __shared__ int s[1024];
    int v = (threadIdx.x < nb) ? g_part[threadIdx.x] : 0;
    s[threadIdx.x] = v;
    __syncthreads();
#pragma unroll
    for (int d = 1; d < 1024; d <<= 1) {
        int t = (threadIdx.x >= d) ? s[threadIdx.x - d] : 0;
        __syncthreads();
        s[threadIdx.x] += t;
        __syncthreads();
    }
    if (threadIdx.x < nb) g_part[threadIdx.x] = s[threadIdx.x] - v;
}

__global__ void k_scan3(int n) {
    int i = blockIdx.x * blockDim.x + threadIdx.x;
    if (i < n) {
        int o = g_off[i] + g_part[i >> 10];
        g_off[i] = o;
        g_pos[i] = o;
    }
}

__global__ void k_place(const void* __restrict__ ei, int E) {
    int e = blockIdx.x * blockDim.x + threadIdx.x;
    if (e < E) {
        int s = edge_at(ei, e);
        int d = edge_at(ei, (long long)E + e);
        int p = atomicAdd(&g_pos[d], 1);
        g_ssrc[p]  = s;
        g_snorm[p] = g_dinv[s] * g_dinv[d];
    }
}

// ---------------------------------------------------------------------------
// SGEMM, fp32 with packed f32x2 FMA (sm_103a FFMA2 path).
// A: [M,K] row-major, B: [K,N] row-major, C: [M,N] row-major.
// RELU_A applies relu to A elements on load (fuses layer-2's relu).
// ---------------------------------------------------------------------------
template <int BM, int BN, int BK, int TM, int TN, bool RELU_A>
__global__ __launch_bounds__((BM / TM) * (BN / TN))
void sgemm_k(const float* __restrict__ A, const float* __restrict__ B,
             float* __restrict__ C, int M, int N, int K)
{
    constexpr int NT  = (BM / TM) * (BN / TN);
    constexpr int TN2 = TN / 2;

    __shared__ __align__(16) float As[BK][BM];   // transposed: As[k][m]
    __shared__ __align__(16) float Bs[BK][BN];

    const int tid = threadIdx.x;
    const int tx  = tid % (BN / TN);
    const int ty  = tid / (BN / TN);
    const int m0  = blockIdx.y * BM;
    const int n0  = blockIdx.x * BN;

    unsigned long long acc[TM][TN2];
#pragma unroll
    for (int i = 0; i < TM; i++)
#pragma unroll
        for (int j = 0; j < TN2; j++) acc[i][j] = 0ull;

    for (int kk = 0; kk < K; kk += BK) {
        for (int i = tid; i < BM * BK / 4; i += NT) {
            int r = i / (BK / 4);
            int c = (i % (BK / 4)) * 4;
            float4 v = make_float4(0.f, 0.f, 0.f, 0.f);
            int row = m0 + r;
            if (row < M)
                v = *reinterpret_cast<const float4*>(
                        &A[(long long)row * K + kk + c]);
            if (RELU_A) {
                v.x = fmaxf(v.x, 0.f); v.y = fmaxf(v.y, 0.f);
                v.z = fmaxf(v.z, 0.f); v.w = fmaxf(v.w, 0.f);
            }
            As[c + 0][r] = v.x; As[c + 1][r] = v.y;
            As[c + 2][r] = v.z; As[c + 3][r] = v.w;
        }
        for (int i = tid; i < BK * BN / 4; i += NT) {
            int r = i / (BN / 4);
            int c = (i % (BN / 4)) * 4;
            *reinterpret_cast<float4*>(&Bs[r][c]) =
                *reinterpret_cast<const float4*>(
                    &B[(long long)(kk + r) * N + n0 + c]);
        }
        __syncthreads();

#pragma unroll
        for (int k = 0; k < BK; k++) {
            float a[TM];
#pragma unroll
            for (int i = 0; i < TM; i += 4) {
                float4 av = *reinterpret_cast<const float4*>(&As[k][ty * TM + i]);
                a[i] = av.x; a[i + 1] = av.y; a[i + 2] = av.z; a[i + 3] = av.w;
            }
            unsigned long long b2[TN2];
            const unsigned long long* bp =
                reinterpret_cast<const unsigned long long*>(&Bs[k][tx * TN]);
#pragma unroll
            for (int j = 0; j < TN2; j++) b2[j] = bp[j];
#pragma unroll
            for (int i = 0; i < TM; i++) {
                unsigned long long a2;
                unsigned int au = __float_as_uint(a[i]);
                asm("mov.b64 %0, {%1, %1};" : "=l"(a2) : "r"(au));
#pragma unroll
                for (int j = 0; j < TN2; j++) {
                    asm("fma.rn.f32x2 %0, %1, %2, %3;"
                        : "=l"(acc[i][j])
                        : "l"(a2), "l"(b2[j]), "l"(acc[i][j]));
                }
            }
        }
        __syncthreads();
    }

#pragma unroll
    for (int i = 0; i < TM; i++) {
        int row = m0 + ty * TM + i;
        if (row >= M) continue;
        float* cp = &C[(long long)row * N + n0 + tx * TN];
#pragma unroll
        for (int j = 0; j < TN2; j++) {
            unsigned int lo, hi;
            asm("mov.b64 {%0, %1}, %2;" : "=r"(lo), "=r"(hi) : "l"(acc[i][j]));
            *reinterpret_cast<float2*>(cp + 2 * j) =
                make_float2(__uint_as_float(lo), __uint_as_float(hi));
        }
    }
}

// ---------------------------------------------------------------------------
// CSR aggregation, no atomics: out[d,:] = dinv[d]^2*h[d,:] + sum_e norm_e*h[src_e,:]
// LPN lanes cooperate on one dst node; each lane owns CPL float4 chunks.
// Edge meta is lane-uniform (L1 broadcast) and streamed (__ldcs); output rows
// streamed (__stcs) so the hot h array keeps L2 residency.
// ---------------------------------------------------------------------------
template <int D4, int LPN, int CPL>
__global__ void k_aggr(const float4* __restrict__ h4,
                       float4* __restrict__ o4, int n)
{
    int gt   = blockIdx.x * blockDim.x + threadIdx.x;
    int node = gt / LPN;
    int lane = threadIdx.x % LPN;
    if (node >= n) return;

    int beg = g_off[node];
    int end = beg + g_cnt[node];
    float w = g_dinv[node];
    w = w * w;

    float4 acc[CPL];
#pragma unroll
    for (int j = 0; j < CPL; j++) {
        float4 v = __ldg(&h4[(long long)node * D4 + lane + j * LPN]);
        acc[j] = make_float4(v.x * w, v.y * w, v.z * w, v.w * w);
    }

    for (int e = beg; e < end; e++) {
        int   s  = __ldcs(&g_ssrc[e]);
        float nm = __ldcs(&g_snorm[e]);
#pragma unroll
        for (int j = 0; j < CPL; j++) {
            float4 v = __ldg(&h4[(long long)s * D4 + lane + j * LPN]);
            acc[j].x += nm * v.x; acc[j].y += nm * v.y;
            acc[j].z += nm * v.z; acc[j].w += nm * v.w;
        }
    }

#pragma unroll
    for (int j = 0; j < CPL; j++)
        __stcs(&o4[(long long)node * D4 + lane + j * LPN], acc[j]);
}

// ---------------------------------------------------------------------------
// Launch
// ---------------------------------------------------------------------------
extern "C" void kernel_launch(void* const* d_in, const int* in_sizes, int n_in,
                              void* d_out, int out_size)
{
    const float* x   = (const float*)d_in[0];   // [N, 512]
    const float* W1  = (const float*)d_in[1];   // [512, 256]
    const float* W2  = (const float*)d_in[2];   // [256, 64]
    const void*  ei  = d_in[3];                 // [2, E] int32 or int64
    float*       out = (float*)d_out;           // [N, 64]

    const int N = in_sizes[0] / INDIM;
    const int E = in_sizes[3] / 2;

    void *ph, *pa1, *ph2;
    cudaGetSymbolAddress(&ph,  g_h);
    cudaGetSymbolAddress(&pa1, g_a1);
    cudaGetSymbolAddress(&ph2, g_h2);
    float* h  = (float*)ph;
    float* a1 = (float*)pa1;
    float* h2 = (float*)ph2;

    const int TB = 256;
    const int NB = (N + 1023) / 1024;           // scan blocks (98 <= 1024)

    // edge dtype + degree count
    k_detect<<<1, 256>>>(ei, E, N);
    k_init  <<<(N + TB - 1) / TB, TB>>>(N);
    k_count <<<(E + TB - 1) / TB, TB>>>(ei, E);

    // layer-1 projection (independent of graph; hoisted for ncu window)
    {
        dim3 grid(HIDDIM / 128, (N + 127) / 128);
        sgemm_k<128, 128, 8, 8, 8, false><<<grid, 256>>>(x, W1, h, N, HIDDIM, INDIM);
    }

    // normalization + CSR build
    k_dinv <<<(N + TB - 1) / TB, TB>>>(N);
    k_scan1<<<NB, 1024>>>(N);
    k_scan2<<<1, 1024>>>(NB);
    k_scan3<<<(N + TB - 1) / TB, TB>>>(N);
    k_place<<<(E + TB - 1) / TB, TB>>>(ei, E);

    // layer-1 aggregation: a1 = D^-1/2 A_hat D^-1/2 h   (32 lanes/node, 2 f4/lane)
    k_aggr<HIDDIM / 4, 32, 2><<<(N * 32 + TB - 1) / TB, TB>>>(
        (const float4*)h, (float4*)a1, N);

    // layer-2 projection: h2 = relu(a1) @ W2 (relu fused into A load)
    {
        dim3 grid(OUTDIM / 64, (N + 127) / 128);
        sgemm_k<128, 64, 8, 8, 4, true><<<grid, 256>>>(a1, W2, h2, N, OUTDIM, HIDDIM);
    }

    // layer-2 aggregation (16 lanes/node, 1 f4/lane)
    k_aggr<OUTDIM / 4, 16, 1><<<(N * 16 + TB - 1) / TB, TB>>>(
        (const float4*)h2, (float4*)out, N);
}